// round 4
// baseline (speedup 1.0000x reference)
#include <cuda_runtime.h>
#include <cuda_fp16.h>

// Problem constants: N=100000, F=16, E=3200000, H=64
#define NN 100000
#define FF 16
#define EE 3200000
#define HH 64

// fp16 scratch tables, one 128-byte row per node (64 halves).
// P[n][j] = sum_k x[n][k]*W1[k][j] + b1[j]   (dst half of concat)
// Q[n][j] = sum_k x[n][k]*W1[16+k][j]        (src half of concat)
__device__ uint4 g_Ph[(size_t)NN * (HH / 8)];   // 12.8 MB
__device__ uint4 g_Qh[(size_t)NN * (HH / 8)];

// ---------------------------------------------------------------------------
// Kernel 1: per-node precompute of P and Q in fp16.
// One thread per (node, j-pair). Weights read as float2 (conflict-free LDS.64).
// ---------------------------------------------------------------------------
__global__ void __launch_bounds__(256)
precompute_kernel(const float* __restrict__ x,
                  const float* __restrict__ W1,
                  const float* __restrict__ b1)
{
    __shared__ float sW1[2 * FF * HH];   // 8 KB
    __shared__ float sb1[HH];
    for (int i = threadIdx.x; i < 2 * FF * HH; i += blockDim.x) sW1[i] = W1[i];
    if (threadIdx.x < HH) sb1[threadIdx.x] = b1[threadIdx.x];
    __syncthreads();

    int idx = blockIdx.x * blockDim.x + threadIdx.x;   // over NN * 32
    if (idx >= NN * (HH / 2)) return;
    int n  = idx >> 5;           // node (whole warp = one node)
    int jp = idx & 31;           // half2 column pair: j0=2*jp, j1=2*jp+1

    const float* xr = x + (size_t)n * FF;
    float p0 = sb1[2 * jp], p1 = sb1[2 * jp + 1];
    float q0 = 0.0f,        q1 = 0.0f;
#pragma unroll
    for (int k = 0; k < FF; k++) {
        float xv = __ldg(xr + k);                        // warp broadcast
        float2 wp = ((const float2*)(sW1 + k * HH))[jp];          // LDS.64
        float2 wq = ((const float2*)(sW1 + (FF + k) * HH))[jp];   // LDS.64
        p0 = fmaf(xv, wp.x, p0);
        p1 = fmaf(xv, wp.y, p1);
        q0 = fmaf(xv, wq.x, q0);
        q1 = fmaf(xv, wq.y, q1);
    }
    ((__half2*)g_Ph)[idx] = __floats2half2_rn(p0, p1);
    ((__half2*)g_Qh)[idx] = __floats2half2_rn(q0, q1);
}

// ---------------------------------------------------------------------------
// Kernel 2: per-edge, 8 threads per edge. Lane sub owns j = 8*sub..8*sub+7,
// so one LDG.128 per lane covers the entire 128B P (and Q) row per edge
// -> 1 L1 wavefront per table per edge.
// x gather fused: lanes 0-3 load x_dst chunks, lanes 4-7 load x_src chunks,
// exchanged via shfl_xor(4). Only lanes 0-3 store the 16-float output.
// ---------------------------------------------------------------------------
__global__ void __launch_bounds__(256)
edge_kernel(const float* __restrict__ x,
            const int* __restrict__ ei,        // [2, E] int32: row0=src, row1=dst
            const float* __restrict__ W2,      // [64,2] row-major
            const float* __restrict__ b2,      // [2]
            float* __restrict__ out)           // [E,16]
{
    __shared__ float sW2a[HH];
    __shared__ float sW2b[HH];
    if (threadIdx.x < HH) {
        sW2a[threadIdx.x] = W2[threadIdx.x * 2 + 0];
        sW2b[threadIdx.x] = W2[threadIdx.x * 2 + 1];
    }
    __syncthreads();

    long long tid = (long long)blockIdx.x * blockDim.x + threadIdx.x;
    long long e   = tid >> 3;
    int sub       = (int)(tid & 7);
    if (e >= EE) return;

    int src = ei[e];
    int dst = ei[(long long)EE + e];

    uint4 pu = (g_Ph + (size_t)dst * (HH / 8))[sub];   // 8 halves
    uint4 qu = (g_Qh + (size_t)src * (HH / 8))[sub];

    // fused x gather: lanes 0-3 -> x_dst, lanes 4-7 -> x_src
    int node = (sub < 4) ? dst : src;
    float4 xv = ((const float4*)(x + (size_t)node * FF))[sub & 3];

    const __half2* ph = (const __half2*)&pu;
    const __half2* qh = (const __half2*)&qu;
    float av = 0.0f, bv = 0.0f;
    const int jb = 8 * sub;
#pragma unroll
    for (int t = 0; t < 4; t++) {
        float2 p2 = __half22float2(ph[t]);
        float2 q2 = __half22float2(qh[t]);
        float h0 = fmaxf(p2.x + q2.x, 0.0f);
        float h1 = fmaxf(p2.y + q2.y, 0.0f);
        int j = jb + 2 * t;
        av = fmaf(h0, sW2a[j],     av);
        av = fmaf(h1, sW2a[j + 1], av);
        bv = fmaf(h0, sW2b[j],     bv);
        bv = fmaf(h1, sW2b[j + 1], bv);
    }

    // reduce the two dots over the 8 lanes of this edge
#pragma unroll
    for (int m = 1; m < 8; m <<= 1) {
        av += __shfl_xor_sync(0xffffffffu, av, m);
        bv += __shfl_xor_sync(0xffffffffu, bv, m);
    }
    av += b2[0];
    bv += b2[1];

    // exchange x chunks across the dst/src halves of the edge group
    float4 xo;
    xo.x = __shfl_xor_sync(0xffffffffu, xv.x, 4);
    xo.y = __shfl_xor_sync(0xffffffffu, xv.y, 4);
    xo.z = __shfl_xor_sync(0xffffffffu, xv.z, 4);
    xo.w = __shfl_xor_sync(0xffffffffu, xv.w, 4);

    if (sub < 4) {   // xv = x_dst chunk, xo = x_src chunk
        float4 o;
        o.x = av * (xv.x - bv * xo.x);
        o.y = av * (xv.y - bv * xo.y);
        o.z = av * (xv.z - bv * xo.z);
        o.w = av * (xv.w - bv * xo.w);
        ((float4*)(out + (size_t)e * FF))[sub] = o;
    }
}

// ---------------------------------------------------------------------------
// Launch
// ---------------------------------------------------------------------------
extern "C" void kernel_launch(void* const* d_in, const int* in_sizes, int n_in,
                              void* d_out, int out_size)
{
    const float* x   = (const float*)d_in[0];   // [N,16]
    const int*   ei  = (const int*)d_in[1];     // [2,E] int32
    const float* W1  = (const float*)d_in[2];   // [32,64]
    const float* b1  = (const float*)d_in[3];   // [64]
    const float* W2  = (const float*)d_in[4];   // [64,2]
    const float* b2  = (const float*)d_in[5];   // [2]
    float*       out = (float*)d_out;           // [E,16]

    (void)in_sizes; (void)n_in; (void)out_size;

    {
        int total = NN * (HH / 2);               // 3.2M threads
        int threads = 256;
        int blocks = (total + threads - 1) / threads;
        precompute_kernel<<<blocks, threads>>>(x, W1, b1);
    }
    {
        long long total = (long long)EE * 8;     // 25.6M threads
        int threads = 256;
        int blocks = (int)((total + threads - 1) / threads);
        edge_kernel<<<blocks, threads>>>(x, ei, W2, b2, out);
    }
}

// round 5
// speedup vs baseline: 1.4190x; 1.4190x over previous
#include <cuda_runtime.h>
#include <cuda_fp16.h>

// Problem constants: N=100000, F=16, E=3200000, H=64
#define NN 100000
#define FF 16
#define EE 3200000
#define HH 64

// fp16 scratch tables, one 128-byte row per node (64 halves).
// P[n][j] = sum_k x[n][k]*W1[k][j] + b1[j]   (dst half of concat)
// Q[n][j] = sum_k x[n][k]*W1[16+k][j]        (src half of concat)
__device__ uint4 g_Ph[(size_t)NN * (HH / 8)];   // 12.8 MB
__device__ uint4 g_Qh[(size_t)NN * (HH / 8)];

// ---------------------------------------------------------------------------
// Kernel 1: per-node precompute of P and Q in fp16.
// One thread per (node, j-pair). Weights read as float2 (conflict-free LDS.64).
// ---------------------------------------------------------------------------
__global__ void __launch_bounds__(256)
precompute_kernel(const float* __restrict__ x,
                  const float* __restrict__ W1,
                  const float* __restrict__ b1)
{
    __shared__ float sW1[2 * FF * HH];   // 8 KB
    __shared__ float sb1[HH];
    for (int i = threadIdx.x; i < 2 * FF * HH; i += blockDim.x) sW1[i] = W1[i];
    if (threadIdx.x < HH) sb1[threadIdx.x] = b1[threadIdx.x];
    __syncthreads();

    int idx = blockIdx.x * blockDim.x + threadIdx.x;   // over NN * 32
    if (idx >= NN * (HH / 2)) return;
    int n  = idx >> 5;           // node (whole warp = one node)
    int jp = idx & 31;           // half2 column pair

    const float* xr = x + (size_t)n * FF;
    float p0 = sb1[2 * jp], p1 = sb1[2 * jp + 1];
    float q0 = 0.0f,        q1 = 0.0f;
#pragma unroll
    for (int k = 0; k < FF; k++) {
        float xv = __ldg(xr + k);                        // warp broadcast
        float2 wp = ((const float2*)(sW1 + k * HH))[jp];
        float2 wq = ((const float2*)(sW1 + (FF + k) * HH))[jp];
        p0 = fmaf(xv, wp.x, p0);
        p1 = fmaf(xv, wp.y, p1);
        q0 = fmaf(xv, wq.x, q0);
        q1 = fmaf(xv, wq.y, q1);
    }
    ((__half2*)g_Ph)[idx] = __floats2half2_rn(p0, p1);
    ((__half2*)g_Qh)[idx] = __floats2half2_rn(q0, q1);
}

// ---------------------------------------------------------------------------
// Kernel 2: 4 threads per edge, 2 edges per thread, loads front-batched
// for MLP ~16. Lane sub owns j = 16*sub .. 16*sub+15 (two uint4 = 16 halves).
//   h = relu(P[dst]+Q[src]); a = h.W2a + b2[0]; b = h.W2b + b2[1]
//   out[e] = a * (x_dst - b * x_src)
// ---------------------------------------------------------------------------
__global__ void __launch_bounds__(256)
edge_kernel(const float* __restrict__ x,
            const int* __restrict__ ei,        // [2, E] int32: row0=src, row1=dst
            const float* __restrict__ W2,      // [64,2] row-major
            const float* __restrict__ b2,      // [2]
            float* __restrict__ out)           // [E,16]
{
    __shared__ float sW2a[HH];
    __shared__ float sW2b[HH];
    if (threadIdx.x < HH) {
        sW2a[threadIdx.x] = W2[threadIdx.x * 2 + 0];
        sW2b[threadIdx.x] = W2[threadIdx.x * 2 + 1];
    }
    __syncthreads();

    long long tid = (long long)blockIdx.x * blockDim.x + threadIdx.x;
    long long g   = tid >> 2;           // edge-pair index
    int sub       = (int)(tid & 3);
    long long e0  = g * 2;
    long long e1  = e0 + 1;
    if (e0 >= EE) return;               // EE is even, e1 valid whenever e0 is

    // ---- front-batched index loads ----
    int src0 = ei[e0];
    int dst0 = ei[(long long)EE + e0];
    int src1 = ei[e1];
    int dst1 = ei[(long long)EE + e1];

    // ---- front-batched gathers (12 independent LDG.128) ----
    const uint4* P0 = g_Ph + (size_t)dst0 * (HH / 8) + sub * 2;
    const uint4* Q0 = g_Qh + (size_t)src0 * (HH / 8) + sub * 2;
    const uint4* P1 = g_Ph + (size_t)dst1 * (HH / 8) + sub * 2;
    const uint4* Q1 = g_Qh + (size_t)src1 * (HH / 8) + sub * 2;
    uint4 pu0a = P0[0], pu0b = P0[1];
    uint4 qu0a = Q0[0], qu0b = Q0[1];
    uint4 pu1a = P1[0], pu1b = P1[1];
    uint4 qu1a = Q1[0], qu1b = Q1[1];

    float4 xd0 = ((const float4*)(x + (size_t)dst0 * FF))[sub];
    float4 xs0 = ((const float4*)(x + (size_t)src0 * FF))[sub];
    float4 xd1 = ((const float4*)(x + (size_t)dst1 * FF))[sub];
    float4 xs1 = ((const float4*)(x + (size_t)src1 * FF))[sub];

    const int jb = 16 * sub;
    float av0 = 0.0f, bv0 = 0.0f, av1 = 0.0f, bv1 = 0.0f;

#pragma unroll
    for (int half = 0; half < 2; half++) {
        const __half2* ph0 = (const __half2*)(half ? &pu0b : &pu0a);
        const __half2* qh0 = (const __half2*)(half ? &qu0b : &qu0a);
        const __half2* ph1 = (const __half2*)(half ? &pu1b : &pu1a);
        const __half2* qh1 = (const __half2*)(half ? &qu1b : &qu1a);
#pragma unroll
        for (int t = 0; t < 4; t++) {
            int j = jb + half * 8 + 2 * t;
            float wa0 = sW2a[j], wa1 = sW2a[j + 1];
            float wb0 = sW2b[j], wb1 = sW2b[j + 1];

            float2 p2 = __half22float2(ph0[t]);
            float2 q2 = __half22float2(qh0[t]);
            float h0 = fmaxf(p2.x + q2.x, 0.0f);
            float h1 = fmaxf(p2.y + q2.y, 0.0f);
            av0 = fmaf(h0, wa0, av0); av0 = fmaf(h1, wa1, av0);
            bv0 = fmaf(h0, wb0, bv0); bv0 = fmaf(h1, wb1, bv0);

            p2 = __half22float2(ph1[t]);
            q2 = __half22float2(qh1[t]);
            h0 = fmaxf(p2.x + q2.x, 0.0f);
            h1 = fmaxf(p2.y + q2.y, 0.0f);
            av1 = fmaf(h0, wa0, av1); av1 = fmaf(h1, wa1, av1);
            bv1 = fmaf(h0, wb0, bv1); bv1 = fmaf(h1, wb1, bv1);
        }
    }

    // reduce dots across the 4 lanes of the group (both edges together)
#pragma unroll
    for (int m = 1; m < 4; m <<= 1) {
        av0 += __shfl_xor_sync(0xffffffffu, av0, m);
        bv0 += __shfl_xor_sync(0xffffffffu, bv0, m);
        av1 += __shfl_xor_sync(0xffffffffu, av1, m);
        bv1 += __shfl_xor_sync(0xffffffffu, bv1, m);
    }
    float b20 = b2[0], b21 = b2[1];
    av0 += b20; bv0 += b21;
    av1 += b20; bv1 += b21;

    // epilogue + stores (warp covers 16 consecutive edges = 1KB contiguous)
    float4 o;
    o.x = av0 * (xd0.x - bv0 * xs0.x);
    o.y = av0 * (xd0.y - bv0 * xs0.y);
    o.z = av0 * (xd0.z - bv0 * xs0.z);
    o.w = av0 * (xd0.w - bv0 * xs0.w);
    ((float4*)(out + (size_t)e0 * FF))[sub] = o;

    o.x = av1 * (xd1.x - bv1 * xs1.x);
    o.y = av1 * (xd1.y - bv1 * xs1.y);
    o.z = av1 * (xd1.z - bv1 * xs1.z);
    o.w = av1 * (xd1.w - bv1 * xs1.w);
    ((float4*)(out + (size_t)e1 * FF))[sub] = o;
}

// ---------------------------------------------------------------------------
// Launch
// ---------------------------------------------------------------------------
extern "C" void kernel_launch(void* const* d_in, const int* in_sizes, int n_in,
                              void* d_out, int out_size)
{
    const float* x   = (const float*)d_in[0];   // [N,16]
    const int*   ei  = (const int*)d_in[1];     // [2,E] int32
    const float* W1  = (const float*)d_in[2];   // [32,64]
    const float* b1  = (const float*)d_in[3];   // [64]
    const float* W2  = (const float*)d_in[4];   // [64,2]
    const float* b2  = (const float*)d_in[5];   // [2]
    float*       out = (float*)d_out;           // [E,16]

    (void)in_sizes; (void)n_in; (void)out_size;

    {
        int total = NN * (HH / 2);               // 3.2M threads
        int threads = 256;
        int blocks = (total + threads - 1) / threads;
        precompute_kernel<<<blocks, threads>>>(x, W1, b1);
    }
    {
        long long total = (long long)(EE / 2) * 4;   // 6.4M threads
        int threads = 256;
        int blocks = (int)((total + threads - 1) / threads);
        edge_kernel<<<blocks, threads>>>(x, ei, W2, b2, out);
    }
}

// round 6
// speedup vs baseline: 1.5426x; 1.0871x over previous
#include <cuda_runtime.h>
#include <cuda_fp16.h>

// Problem constants: N=100000, F=16, E=3200000, H=64
#define NN 100000
#define FF 16
#define EE 3200000
#define HH 64

// fp16 scratch tables, one 128-byte row per node (64 halves).
// P[n][j] = sum_k x[n][k]*W1[k][j] + b1[j]   (dst half of concat)
// Q[n][j] = sum_k x[n][k]*W1[16+k][j]        (src half of concat)
__device__ uint4 g_Ph[(size_t)NN * (HH / 8)];   // 12.8 MB
__device__ uint4 g_Qh[(size_t)NN * (HH / 8)];

// ---------------------------------------------------------------------------
// Kernel 1: per-node precompute of P and Q in fp16. Grid-stride so the 8KB
// smem W1 staging is amortized over many nodes per block.
// ---------------------------------------------------------------------------
__global__ void __launch_bounds__(256)
precompute_kernel(const float* __restrict__ x,
                  const float* __restrict__ W1,
                  const float* __restrict__ b1)
{
    __shared__ float sW1[2 * FF * HH];   // 8 KB
    __shared__ float sb1[HH];
    for (int i = threadIdx.x; i < 2 * FF * HH; i += blockDim.x) sW1[i] = W1[i];
    if (threadIdx.x < HH) sb1[threadIdx.x] = b1[threadIdx.x];
    __syncthreads();

    const int total  = NN * (HH / 2);                 // 3.2M (node, half2-pair)
    const int stride = gridDim.x * blockDim.x;
    for (int idx = blockIdx.x * blockDim.x + threadIdx.x; idx < total; idx += stride) {
        int n  = idx >> 5;           // node (warp = one node)
        int jp = idx & 31;           // half2 column pair

        const float* xr = x + (size_t)n * FF;
        float p0 = sb1[2 * jp], p1 = sb1[2 * jp + 1];
        float q0 = 0.0f,        q1 = 0.0f;
#pragma unroll
        for (int k = 0; k < FF; k++) {
            float xv = __ldg(xr + k);                        // warp broadcast
            float2 wp = ((const float2*)(sW1 + k * HH))[jp];
            float2 wq = ((const float2*)(sW1 + (FF + k) * HH))[jp];
            p0 = fmaf(xv, wp.x, p0);
            p1 = fmaf(xv, wp.y, p1);
            q0 = fmaf(xv, wq.x, q0);
            q1 = fmaf(xv, wq.y, q1);
        }
        ((__half2*)g_Ph)[idx] = __floats2half2_rn(p0, p1);
        ((__half2*)g_Qh)[idx] = __floats2half2_rn(q0, q1);
    }
}

// ---------------------------------------------------------------------------
// Kernel 2: 8 lanes per edge, 2 edges per thread, loads front-batched.
// Lane sub owns j = 8*sub .. 8*sub+7: ONE LDG.128 covers the whole 128B
// P (or Q) row per edge -> 1 L1 wavefront per table per edge.
// x is read as per-lane float2 at element 2*sub (no exchange shuffles) and
// each lane stores a float2 of the 16-float output row.
// ---------------------------------------------------------------------------
__global__ void __launch_bounds__(256)
edge_kernel(const float* __restrict__ x,
            const int* __restrict__ ei,        // [2, E] int32: row0=src, row1=dst
            const float* __restrict__ W2,      // [64,2] row-major
            const float* __restrict__ b2,      // [2]
            float* __restrict__ out)           // [E,16]
{
    __shared__ float sW2a[HH];
    __shared__ float sW2b[HH];
    if (threadIdx.x < HH) {
        sW2a[threadIdx.x] = W2[threadIdx.x * 2 + 0];
        sW2b[threadIdx.x] = W2[threadIdx.x * 2 + 1];
    }
    __syncthreads();

    long long tid = (long long)blockIdx.x * blockDim.x + threadIdx.x;
    long long grp = tid >> 3;            // 8-lane group = 2 consecutive edges
    int sub       = (int)(tid & 7);
    long long e0  = grp * 2;
    long long e1  = e0 + 1;
    if (e0 >= EE) return;                // EE even -> e1 valid with e0

    // ---- front-batched index loads ----
    int src0 = ei[e0];
    int dst0 = ei[(long long)EE + e0];
    int src1 = ei[e1];
    int dst1 = ei[(long long)EE + e1];

    // ---- front-batched gathers: 4 full-row LDG.128 + 4 float2 x loads ----
    uint4 pu0 = g_Ph[(size_t)dst0 * (HH / 8) + sub];
    uint4 qu0 = g_Qh[(size_t)src0 * (HH / 8) + sub];
    uint4 pu1 = g_Ph[(size_t)dst1 * (HH / 8) + sub];
    uint4 qu1 = g_Qh[(size_t)src1 * (HH / 8) + sub];

    float2 xd0 = ((const float2*)(x + (size_t)dst0 * FF))[sub];
    float2 xs0 = ((const float2*)(x + (size_t)src0 * FF))[sub];
    float2 xd1 = ((const float2*)(x + (size_t)dst1 * FF))[sub];
    float2 xs1 = ((const float2*)(x + (size_t)src1 * FF))[sub];

    // ---- per-lane partial dots over j = 8*sub .. 8*sub+7 ----
    const __half2* ph0 = (const __half2*)&pu0;
    const __half2* qh0 = (const __half2*)&qu0;
    const __half2* ph1 = (const __half2*)&pu1;
    const __half2* qh1 = (const __half2*)&qu1;
    const int jb = 8 * sub;
    float av0 = 0.0f, bv0 = 0.0f, av1 = 0.0f, bv1 = 0.0f;
#pragma unroll
    for (int t = 0; t < 4; t++) {
        int j = jb + 2 * t;
        float wa0 = sW2a[j], wa1 = sW2a[j + 1];
        float wb0 = sW2b[j], wb1 = sW2b[j + 1];

        float2 p2 = __half22float2(ph0[t]);
        float2 q2 = __half22float2(qh0[t]);
        float h0 = fmaxf(p2.x + q2.x, 0.0f);
        float h1 = fmaxf(p2.y + q2.y, 0.0f);
        av0 = fmaf(h0, wa0, av0); av0 = fmaf(h1, wa1, av0);
        bv0 = fmaf(h0, wb0, bv0); bv0 = fmaf(h1, wb1, bv0);

        p2 = __half22float2(ph1[t]);
        q2 = __half22float2(qh1[t]);
        h0 = fmaxf(p2.x + q2.x, 0.0f);
        h1 = fmaxf(p2.y + q2.y, 0.0f);
        av1 = fmaf(h0, wa0, av1); av1 = fmaf(h1, wa1, av1);
        bv1 = fmaf(h0, wb0, bv1); bv1 = fmaf(h1, wb1, bv1);
    }

    // ---- reduce over the 8 lanes of this group (stays within group) ----
#pragma unroll
    for (int m = 1; m < 8; m <<= 1) {
        av0 += __shfl_xor_sync(0xffffffffu, av0, m);
        bv0 += __shfl_xor_sync(0xffffffffu, bv0, m);
        av1 += __shfl_xor_sync(0xffffffffu, av1, m);
        bv1 += __shfl_xor_sync(0xffffffffu, bv1, m);
    }
    float b20 = b2[0], b21 = b2[1];
    av0 += b20; bv0 += b21;
    av1 += b20; bv1 += b21;

    // ---- epilogue: each lane owns output elements 2*sub, 2*sub+1 ----
    float2 o0, o1;
    o0.x = av0 * (xd0.x - bv0 * xs0.x);
    o0.y = av0 * (xd0.y - bv0 * xs0.y);
    o1.x = av1 * (xd1.x - bv1 * xs1.x);
    o1.y = av1 * (xd1.y - bv1 * xs1.y);
    ((float2*)(out + (size_t)e0 * FF))[sub] = o0;
    ((float2*)(out + (size_t)e1 * FF))[sub] = o1;
}

// ---------------------------------------------------------------------------
// Launch
// ---------------------------------------------------------------------------
extern "C" void kernel_launch(void* const* d_in, const int* in_sizes, int n_in,
                              void* d_out, int out_size)
{
    const float* x   = (const float*)d_in[0];   // [N,16]
    const int*   ei  = (const int*)d_in[1];     // [2,E] int32
    const float* W1  = (const float*)d_in[2];   // [32,64]
    const float* b1  = (const float*)d_in[3];   // [64]
    const float* W2  = (const float*)d_in[4];   // [64,2]
    const float* b2  = (const float*)d_in[5];   // [2]
    float*       out = (float*)d_out;           // [E,16]

    (void)in_sizes; (void)n_in; (void)out_size;

    precompute_kernel<<<2048, 256>>>(x, W1, b1);

    {
        long long total = (long long)(EE / 2) * 8;   // 12.8M threads
        int threads = 256;
        int blocks = (int)((total + threads - 1) / threads);
        edge_kernel<<<blocks, threads>>>(x, ei, W2, b2, out);
    }
}

// round 7
// speedup vs baseline: 1.8835x; 1.2210x over previous
#include <cuda_runtime.h>
#include <cuda_fp16.h>

// Problem constants: N=100000, F=16, E=3200000, H=64
#define NN 100000
#define FF 16
#define EE 3200000
#define HH 64

// fp16 scratch tables, one 128-byte row per node (64 halves).
// P[n][j] = sum_k x[n][k]*W1[k][j] + b1[j]   (dst half of concat)
// Q[n][j] = sum_k x[n][k]*W1[16+k][j]        (src half of concat)
__device__ uint4 g_Ph[(size_t)NN * (HH / 8)];   // 12.8 MB
__device__ uint4 g_Qh[(size_t)NN * (HH / 8)];

// ---------------------------------------------------------------------------
// Kernel 1: precompute P,Q in fp16. 4 nodes per thread so every smem weight
// read (LDS.64) is reused 4x -> smem traffic /4 (was the 23us floor).
// Thread = (node-quad, jp). x read as float4 chunks (4 k's at a time).
// ---------------------------------------------------------------------------
__global__ void __launch_bounds__(256)
precompute_kernel(const float* __restrict__ x,
                  const float* __restrict__ W1,
                  const float* __restrict__ b1)
{
    __shared__ float sW1[2 * FF * HH];   // 8 KB
    __shared__ float sb1[HH];
    for (int i = threadIdx.x; i < 2 * FF * HH; i += blockDim.x) sW1[i] = W1[i];
    if (threadIdx.x < HH) sb1[threadIdx.x] = b1[threadIdx.x];
    __syncthreads();

    const int total  = (NN / 4) * 32;                // 800K (node-quad, jp)
    const int stride = gridDim.x * blockDim.x;
    for (int idx = blockIdx.x * blockDim.x + threadIdx.x; idx < total; idx += stride) {
        int nq = idx >> 5;            // node quad (warp = one quad)
        int jp = idx & 31;            // half2 column pair
        int n0 = nq * 4;

        float bias0 = sb1[2 * jp], bias1 = sb1[2 * jp + 1];
        float p0[4], p1[4], q0[4], q1[4];
#pragma unroll
        for (int nn = 0; nn < 4; nn++) {
            p0[nn] = bias0; p1[nn] = bias1; q0[nn] = 0.0f; q1[nn] = 0.0f;
        }

#pragma unroll
        for (int kc = 0; kc < 4; kc++) {             // k chunk of 4
            float4 xv[4];
#pragma unroll
            for (int nn = 0; nn < 4; nn++)
                xv[nn] = __ldg((const float4*)(x + (size_t)(n0 + nn) * FF) + kc);
#pragma unroll
            for (int kk = 0; kk < 4; kk++) {
                int k = kc * 4 + kk;
                float2 wp = ((const float2*)(sW1 + k * HH))[jp];
                float2 wq = ((const float2*)(sW1 + (FF + k) * HH))[jp];
#pragma unroll
                for (int nn = 0; nn < 4; nn++) {
                    float xs = (kk == 0) ? xv[nn].x : (kk == 1) ? xv[nn].y
                             : (kk == 2) ? xv[nn].z : xv[nn].w;
                    p0[nn] = fmaf(xs, wp.x, p0[nn]);
                    p1[nn] = fmaf(xs, wp.y, p1[nn]);
                    q0[nn] = fmaf(xs, wq.x, q0[nn]);
                    q1[nn] = fmaf(xs, wq.y, q1[nn]);
                }
            }
        }
#pragma unroll
        for (int nn = 0; nn < 4; nn++) {
            int o = (n0 + nn) * 32 + jp;
            ((__half2*)g_Ph)[o] = __floats2half2_rn(p0[nn], p1[nn]);
            ((__half2*)g_Qh)[o] = __floats2half2_rn(q0[nn], q1[nn]);
        }
    }
}

// ---------------------------------------------------------------------------
// Kernel 2: 8 lanes per group, 2 edges per group. Lane sub owns
// j = 8*sub..8*sub+7 for both edges' dots (P/Q rows are 1 LDG.128 / 1 wf).
// Epilogue split: lanes 0-3 own edge e0, lanes 4-7 own edge e1 ->
// x loads are 2 float4 instr, store is 1 float4 instr (512B/warp contiguous).
// ---------------------------------------------------------------------------
__global__ void __launch_bounds__(256)
edge_kernel(const float* __restrict__ x,
            const int* __restrict__ ei,        // [2, E] int32: row0=src, row1=dst
            const float* __restrict__ W2,      // [64,2] row-major
            const float* __restrict__ b2,      // [2]
            float* __restrict__ out)           // [E,16]
{
    __shared__ float sW2a[HH];
    __shared__ float sW2b[HH];
    if (threadIdx.x < HH) {
        sW2a[threadIdx.x] = W2[threadIdx.x * 2 + 0];
        sW2b[threadIdx.x] = W2[threadIdx.x * 2 + 1];
    }
    __syncthreads();

    long long tid = (long long)blockIdx.x * blockDim.x + threadIdx.x;
    long long grp = tid >> 3;            // group = 2 consecutive edges
    int sub       = (int)(tid & 7);
    long long e0  = grp * 2;
    if (e0 >= EE) return;                // EE even -> e1 valid with e0

    // ---- index loads (int2: e0,e1 adjacent) ----
    int2 s01 = ((const int2*)ei)[grp];                 // src of e0,e1
    int2 d01 = ((const int2*)ei)[(EE >> 1) + grp];     // dst of e0,e1
    int src0 = s01.x, src1 = s01.y;
    int dst0 = d01.x, dst1 = d01.y;

    // ---- front-batched gathers ----
    uint4 pu0 = g_Ph[(size_t)dst0 * (HH / 8) + sub];
    uint4 qu0 = g_Qh[(size_t)src0 * (HH / 8) + sub];
    uint4 pu1 = g_Ph[(size_t)dst1 * (HH / 8) + sub];
    uint4 qu1 = g_Qh[(size_t)src1 * (HH / 8) + sub];

    bool lo = (sub < 4);
    int dN = lo ? dst0 : dst1;
    int sN = lo ? src0 : src1;
    float4 xd = ((const float4*)(x + (size_t)dN * FF))[sub & 3];
    float4 xs = ((const float4*)(x + (size_t)sN * FF))[sub & 3];

    // ---- per-lane partial dots over j = 8*sub .. 8*sub+7 ----
    const __half2* ph0 = (const __half2*)&pu0;
    const __half2* qh0 = (const __half2*)&qu0;
    const __half2* ph1 = (const __half2*)&pu1;
    const __half2* qh1 = (const __half2*)&qu1;
    const int jb = 8 * sub;
    float av0 = 0.0f, bv0 = 0.0f, av1 = 0.0f, bv1 = 0.0f;
#pragma unroll
    for (int t = 0; t < 4; t++) {
        int j = jb + 2 * t;
        float wa0 = sW2a[j], wa1 = sW2a[j + 1];
        float wb0 = sW2b[j], wb1 = sW2b[j + 1];

        float2 p2 = __half22float2(ph0[t]);
        float2 q2 = __half22float2(qh0[t]);
        float h0 = fmaxf(p2.x + q2.x, 0.0f);
        float h1 = fmaxf(p2.y + q2.y, 0.0f);
        av0 = fmaf(h0, wa0, av0); av0 = fmaf(h1, wa1, av0);
        bv0 = fmaf(h0, wb0, bv0); bv0 = fmaf(h1, wb1, bv0);

        p2 = __half22float2(ph1[t]);
        q2 = __half22float2(qh1[t]);
        h0 = fmaxf(p2.x + q2.x, 0.0f);
        h1 = fmaxf(p2.y + q2.y, 0.0f);
        av1 = fmaf(h0, wa0, av1); av1 = fmaf(h1, wa1, av1);
        bv1 = fmaf(h0, wb0, bv1); bv1 = fmaf(h1, wb1, bv1);
    }

    // ---- reduce: 2 butterfly rounds on all 4 values, then select-swap ----
#pragma unroll
    for (int m = 1; m < 4; m <<= 1) {
        av0 += __shfl_xor_sync(0xffffffffu, av0, m);
        bv0 += __shfl_xor_sync(0xffffffffu, bv0, m);
        av1 += __shfl_xor_sync(0xffffffffu, av1, m);
        bv1 += __shfl_xor_sync(0xffffffffu, bv1, m);
    }
    // lo lanes send their av1/bv1 quad-partials, receive hi's av0/bv0 partials
    float va = lo ? av1 : av0;
    float vb = lo ? bv1 : bv0;
    float ra = __shfl_xor_sync(0xffffffffu, va, 4);
    float rb = __shfl_xor_sync(0xffffffffu, vb, 4);
    float a  = (lo ? av0 : av1) + ra + b2[0];
    float b  = (lo ? bv0 : bv1) + rb + b2[1];

    // ---- epilogue: lane owns 4 floats of its edge's 16-float output ----
    long long e = lo ? e0 : (e0 + 1);
    float4 o;
    o.x = a * (xd.x - b * xs.x);
    o.y = a * (xd.y - b * xs.y);
    o.z = a * (xd.z - b * xs.z);
    o.w = a * (xd.w - b * xs.w);
    ((float4*)(out + (size_t)e * FF))[sub & 3] = o;
}

// ---------------------------------------------------------------------------
// Launch
// ---------------------------------------------------------------------------
extern "C" void kernel_launch(void* const* d_in, const int* in_sizes, int n_in,
                              void* d_out, int out_size)
{
    const float* x   = (const float*)d_in[0];   // [N,16]
    const int*   ei  = (const int*)d_in[1];     // [2,E] int32
    const float* W1  = (const float*)d_in[2];   // [32,64]
    const float* b1  = (const float*)d_in[3];   // [64]
    const float* W2  = (const float*)d_in[4];   // [64,2]
    const float* b2  = (const float*)d_in[5];   // [2]
    float*       out = (float*)d_out;           // [E,16]

    (void)in_sizes; (void)n_in; (void)out_size;

    precompute_kernel<<<1184, 256>>>(x, W1, b1);

    {
        long long total = (long long)(EE / 2) * 8;   // 12.8M threads
        int threads = 256;
        int blocks = (int)((total + threads - 1) / threads);
        edge_kernel<<<blocks, threads>>>(x, ei, W2, b2, out);
    }
}

// round 8
// speedup vs baseline: 1.9079x; 1.0130x over previous
#include <cuda_runtime.h>
#include <cuda_fp16.h>

// Problem constants: N=100000, F=16, E=3200000, H=64
#define NN 100000
#define FF 16
#define EE 3200000
#define HH 64

// fp16 scratch tables, one 128-byte row per node (64 halves).
// P[n][j] = sum_k x[n][k]*W1[k][j] + b1[j]   (dst half of concat)
// Q[n][j] = sum_k x[n][k]*W1[16+k][j]        (src half of concat)
__device__ uint4 g_Ph[(size_t)NN * (HH / 8)];   // 12.8 MB
__device__ uint4 g_Qh[(size_t)NN * (HH / 8)];

// ---------------------------------------------------------------------------
// Kernel 1: precompute P,Q in fp16. 4 nodes per thread so every smem weight
// read (LDS.64) is reused 4x.
// ---------------------------------------------------------------------------
__global__ void __launch_bounds__(256)
precompute_kernel(const float* __restrict__ x,
                  const float* __restrict__ W1,
                  const float* __restrict__ b1)
{
    __shared__ float sW1[2 * FF * HH];   // 8 KB
    __shared__ float sb1[HH];
    for (int i = threadIdx.x; i < 2 * FF * HH; i += blockDim.x) sW1[i] = W1[i];
    if (threadIdx.x < HH) sb1[threadIdx.x] = b1[threadIdx.x];
    __syncthreads();

    const int total  = (NN / 4) * 32;                // 800K (node-quad, jp)
    const int stride = gridDim.x * blockDim.x;
    for (int idx = blockIdx.x * blockDim.x + threadIdx.x; idx < total; idx += stride) {
        int nq = idx >> 5;            // node quad (warp = one quad)
        int jp = idx & 31;            // half2 column pair
        int n0 = nq * 4;

        float bias0 = sb1[2 * jp], bias1 = sb1[2 * jp + 1];
        float p0[4], p1[4], q0[4], q1[4];
#pragma unroll
        for (int nn = 0; nn < 4; nn++) {
            p0[nn] = bias0; p1[nn] = bias1; q0[nn] = 0.0f; q1[nn] = 0.0f;
        }

#pragma unroll
        for (int kc = 0; kc < 4; kc++) {             // k chunk of 4
            float4 xv[4];
#pragma unroll
            for (int nn = 0; nn < 4; nn++)
                xv[nn] = __ldg((const float4*)(x + (size_t)(n0 + nn) * FF) + kc);
#pragma unroll
            for (int kk = 0; kk < 4; kk++) {
                int k = kc * 4 + kk;
                float2 wp = ((const float2*)(sW1 + k * HH))[jp];
                float2 wq = ((const float2*)(sW1 + (FF + k) * HH))[jp];
#pragma unroll
                for (int nn = 0; nn < 4; nn++) {
                    float xs = (kk == 0) ? xv[nn].x : (kk == 1) ? xv[nn].y
                             : (kk == 2) ? xv[nn].z : xv[nn].w;
                    p0[nn] = fmaf(xs, wp.x, p0[nn]);
                    p1[nn] = fmaf(xs, wp.y, p1[nn]);
                    q0[nn] = fmaf(xs, wq.x, q0[nn]);
                    q1[nn] = fmaf(xs, wq.y, q1[nn]);
                }
            }
        }
#pragma unroll
        for (int nn = 0; nn < 4; nn++) {
            int o = (n0 + nn) * 32 + jp;
            ((__half2*)g_Ph)[o] = __floats2half2_rn(p0[nn], p1[nn]);
            ((__half2*)g_Qh)[o] = __floats2half2_rn(q0[nn], q1[nn]);
        }
    }
}

// ---------------------------------------------------------------------------
// Kernel 2: 8 lanes per group, 2 edges per group (R7 structure).
// W2 in smem as interleaved fp16 pairs half2(wa_j, wb_j): each lane reads its
// 8 pairs as 2 LDS.128 (32B contiguous), warp span 256B -> 4 wf/warp vs 16.
// ---------------------------------------------------------------------------
__global__ void __launch_bounds__(256)
edge_kernel(const float* __restrict__ x,
            const int* __restrict__ ei,        // [2, E] int32: row0=src, row1=dst
            const float* __restrict__ W2,      // [64,2] row-major
            const float* __restrict__ b2,      // [2]
            float* __restrict__ out)           // [E,16]
{
    __shared__ __half2 sW2h[HH];               // (wa_j, wb_j) per j, 256B
    if (threadIdx.x < HH) {
        sW2h[threadIdx.x] = __floats2half2_rn(W2[threadIdx.x * 2 + 0],
                                              W2[threadIdx.x * 2 + 1]);
    }
    __syncthreads();

    long long tid = (long long)blockIdx.x * blockDim.x + threadIdx.x;
    long long grp = tid >> 3;            // group = 2 consecutive edges
    int sub       = (int)(tid & 7);
    long long e0  = grp * 2;
    if (e0 >= EE) return;                // EE even -> e1 valid with e0

    // ---- index loads (int2: e0,e1 adjacent) ----
    int2 s01 = ((const int2*)ei)[grp];                 // src of e0,e1
    int2 d01 = ((const int2*)ei)[(EE >> 1) + grp];     // dst of e0,e1
    int src0 = s01.x, src1 = s01.y;
    int dst0 = d01.x, dst1 = d01.y;

    // ---- front-batched gathers ----
    uint4 pu0 = g_Ph[(size_t)dst0 * (HH / 8) + sub];
    uint4 qu0 = g_Qh[(size_t)src0 * (HH / 8) + sub];
    uint4 pu1 = g_Ph[(size_t)dst1 * (HH / 8) + sub];
    uint4 qu1 = g_Qh[(size_t)src1 * (HH / 8) + sub];

    bool lo = (sub < 4);
    int dN = lo ? dst0 : dst1;
    int sN = lo ? src0 : src1;
    float4 xd = ((const float4*)(x + (size_t)dN * FF))[sub & 3];
    float4 xs = ((const float4*)(x + (size_t)sN * FF))[sub & 3];

    // ---- W2 pairs for this lane's j range: 2 LDS.128, kept as one array ----
    const int jb = 8 * sub;
    uint4 w[2];
    w[0] = ((const uint4*)(sW2h + jb))[0];   // j = jb   .. jb+3
    w[1] = ((const uint4*)(sW2h + jb))[1];   // j = jb+4 .. jb+7
    const __half2* wv = (const __half2*)w;   // 8 contiguous (wa,wb) pairs

    // ---- per-lane partial dots over j = 8*sub .. 8*sub+7 ----
    const __half2* ph0 = (const __half2*)&pu0;
    const __half2* qh0 = (const __half2*)&qu0;
    const __half2* ph1 = (const __half2*)&pu1;
    const __half2* qh1 = (const __half2*)&qu1;
    float av0 = 0.0f, bv0 = 0.0f, av1 = 0.0f, bv1 = 0.0f;
#pragma unroll
    for (int t = 0; t < 4; t++) {
        float2 wab0 = __half22float2(wv[2 * t]);       // (wa,wb) for j=jb+2t
        float2 wab1 = __half22float2(wv[2 * t + 1]);   // (wa,wb) for j=jb+2t+1

        float2 p2 = __half22float2(ph0[t]);
        float2 q2 = __half22float2(qh0[t]);
        float h0 = fmaxf(p2.x + q2.x, 0.0f);
        float h1 = fmaxf(p2.y + q2.y, 0.0f);
        av0 = fmaf(h0, wab0.x, av0); av0 = fmaf(h1, wab1.x, av0);
        bv0 = fmaf(h0, wab0.y, bv0); bv0 = fmaf(h1, wab1.y, bv0);

        p2 = __half22float2(ph1[t]);
        q2 = __half22float2(qh1[t]);
        h0 = fmaxf(p2.x + q2.x, 0.0f);
        h1 = fmaxf(p2.y + q2.y, 0.0f);
        av1 = fmaf(h0, wab0.x, av1); av1 = fmaf(h1, wab1.x, av1);
        bv1 = fmaf(h0, wab0.y, bv1); bv1 = fmaf(h1, wab1.y, bv1);
    }

    // ---- reduce: 2 butterfly rounds, then select-swap across halves ----
#pragma unroll
    for (int m = 1; m < 4; m <<= 1) {
        av0 += __shfl_xor_sync(0xffffffffu, av0, m);
        bv0 += __shfl_xor_sync(0xffffffffu, bv0, m);
        av1 += __shfl_xor_sync(0xffffffffu, av1, m);
        bv1 += __shfl_xor_sync(0xffffffffu, bv1, m);
    }
    float va = lo ? av1 : av0;
    float vb = lo ? bv1 : bv0;
    float ra = __shfl_xor_sync(0xffffffffu, va, 4);
    float rb = __shfl_xor_sync(0xffffffffu, vb, 4);
    float a  = (lo ? av0 : av1) + ra + b2[0];
    float b  = (lo ? bv0 : bv1) + rb + b2[1];

    // ---- epilogue: lane owns 4 floats of its edge's 16-float output ----
    long long e = lo ? e0 : (e0 + 1);
    float4 o;
    o.x = a * (xd.x - b * xs.x);
    o.y = a * (xd.y - b * xs.y);
    o.z = a * (xd.z - b * xs.z);
    o.w = a * (xd.w - b * xs.w);
    ((float4*)(out + (size_t)e * FF))[sub & 3] = o;
}

// ---------------------------------------------------------------------------
// Launch
// ---------------------------------------------------------------------------
extern "C" void kernel_launch(void* const* d_in, const int* in_sizes, int n_in,
                              void* d_out, int out_size)
{
    const float* x   = (const float*)d_in[0];   // [N,16]
    const int*   ei  = (const int*)d_in[1];     // [2,E] int32
    const float* W1  = (const float*)d_in[2];   // [32,64]
    const float* b1  = (const float*)d_in[3];   // [64]
    const float* W2  = (const float*)d_in[4];   // [64,2]
    const float* b2  = (const float*)d_in[5];   // [2]
    float*       out = (float*)d_out;           // [E,16]

    (void)in_sizes; (void)n_in; (void)out_size;

    precompute_kernel<<<1184, 256>>>(x, W1, b1);

    {
        long long total = (long long)(EE / 2) * 8;   // 12.8M threads
        int threads = 256;
        int blocks = (int)((total + threads - 1) / threads);
        edge_kernel<<<blocks, threads>>>(x, ei, W2, b2, out);
    }
}

// round 9
// speedup vs baseline: 2.1996x; 1.1529x over previous
#include <cuda_runtime.h>
#include <cuda_fp16.h>

// Problem constants: N=100000, F=16, E=3200000, H=64
#define NN 100000
#define FF 16
#define EE 3200000
#define HH 64

// fp16 scratch tables, one 128-byte row per node (64 halves).
// P[n][j] = sum_k x[n][k]*W1[k][j] + b1[j]   (dst half of concat)
// Q[n][j] = sum_k x[n][k]*W1[16+k][j]        (src half of concat)
__device__ uint4 g_Ph[(size_t)NN * (HH / 8)];   // 12.8 MB
__device__ uint4 g_Qh[(size_t)NN * (HH / 8)];

// ---------------------------------------------------------------------------
// Kernel 1: precompute P,Q in fp16. 4 nodes per thread so every smem weight
// read (LDS.64) is reused 4x.
// ---------------------------------------------------------------------------
__global__ void __launch_bounds__(256)
precompute_kernel(const float* __restrict__ x,
                  const float* __restrict__ W1,
                  const float* __restrict__ b1)
{
    __shared__ float sW1[2 * FF * HH];   // 8 KB
    __shared__ float sb1[HH];
    for (int i = threadIdx.x; i < 2 * FF * HH; i += blockDim.x) sW1[i] = W1[i];
    if (threadIdx.x < HH) sb1[threadIdx.x] = b1[threadIdx.x];
    __syncthreads();

    const int total  = (NN / 4) * 32;                // 800K (node-quad, jp)
    const int stride = gridDim.x * blockDim.x;
    for (int idx = blockIdx.x * blockDim.x + threadIdx.x; idx < total; idx += stride) {
        int nq = idx >> 5;            // node quad (warp = one quad)
        int jp = idx & 31;            // half2 column pair
        int n0 = nq * 4;

        float bias0 = sb1[2 * jp], bias1 = sb1[2 * jp + 1];
        float p0[4], p1[4], q0[4], q1[4];
#pragma unroll
        for (int nn = 0; nn < 4; nn++) {
            p0[nn] = bias0; p1[nn] = bias1; q0[nn] = 0.0f; q1[nn] = 0.0f;
        }

#pragma unroll
        for (int kc = 0; kc < 4; kc++) {             // k chunk of 4
            float4 xv[4];
#pragma unroll
            for (int nn = 0; nn < 4; nn++)
                xv[nn] = __ldg((const float4*)(x + (size_t)(n0 + nn) * FF) + kc);
#pragma unroll
            for (int kk = 0; kk < 4; kk++) {
                int k = kc * 4 + kk;
                float2 wp = ((const float2*)(sW1 + k * HH))[jp];
                float2 wq = ((const float2*)(sW1 + (FF + k) * HH))[jp];
#pragma unroll
                for (int nn = 0; nn < 4; nn++) {
                    float xs = (kk == 0) ? xv[nn].x : (kk == 1) ? xv[nn].y
                             : (kk == 2) ? xv[nn].z : xv[nn].w;
                    p0[nn] = fmaf(xs, wp.x, p0[nn]);
                    p1[nn] = fmaf(xs, wp.y, p1[nn]);
                    q0[nn] = fmaf(xs, wq.x, q0[nn]);
                    q1[nn] = fmaf(xs, wq.y, q1[nn]);
                }
            }
        }
#pragma unroll
        for (int nn = 0; nn < 4; nn++) {
            int o = (n0 + nn) * 32 + jp;
            ((__half2*)g_Ph)[o] = __floats2half2_rn(p0[nn], p1[nn]);
            ((__half2*)g_Qh)[o] = __floats2half2_rn(q0[nn], q1[nn]);
        }
    }
}

// ---------------------------------------------------------------------------
// Kernel 2: 8 lanes per group, 2 edges per group. Dot products computed in
// packed half2 (HADD2/HMAX2/HFMA2, only 4 terms per fp16 accumulator lane),
// converted to fp32 for the cross-lane reduction and epilogue.
// Weights deinterleaved into half2 tables sWa/sWb: 1 LDS.128 each per lane,
// warp span 128B -> 1 wavefront each.
// ---------------------------------------------------------------------------
__global__ void __launch_bounds__(256)
edge_kernel(const float* __restrict__ x,
            const int* __restrict__ ei,        // [2, E] int32: row0=src, row1=dst
            const float* __restrict__ W2,      // [64,2] row-major
            const float* __restrict__ b2,      // [2]
            float* __restrict__ out)           // [E,16]
{
    __shared__ __half2 sWa[HH / 2];            // (wa_{2i}, wa_{2i+1}), 128B
    __shared__ __half2 sWb[HH / 2];            // (wb_{2i}, wb_{2i+1}), 128B
    if (threadIdx.x < 32) {
        int i = threadIdx.x;
        sWa[i] = __floats2half2_rn(W2[4 * i + 0], W2[4 * i + 2]);
        sWb[i] = __floats2half2_rn(W2[4 * i + 1], W2[4 * i + 3]);
    }
    __syncthreads();

    long long tid = (long long)blockIdx.x * blockDim.x + threadIdx.x;
    long long grp = tid >> 3;            // group = 2 consecutive edges
    int sub       = (int)(tid & 7);
    long long e0  = grp * 2;
    if (e0 >= EE) return;                // EE even -> e1 valid with e0

    // ---- index loads (int2: e0,e1 adjacent) ----
    int2 s01 = ((const int2*)ei)[grp];                 // src of e0,e1
    int2 d01 = ((const int2*)ei)[(EE >> 1) + grp];     // dst of e0,e1
    int src0 = s01.x, src1 = s01.y;
    int dst0 = d01.x, dst1 = d01.y;

    // ---- front-batched gathers ----
    uint4 pu0 = g_Ph[(size_t)dst0 * (HH / 8) + sub];
    uint4 qu0 = g_Qh[(size_t)src0 * (HH / 8) + sub];
    uint4 pu1 = g_Ph[(size_t)dst1 * (HH / 8) + sub];
    uint4 qu1 = g_Qh[(size_t)src1 * (HH / 8) + sub];

    bool lo = (sub < 4);
    int dN = lo ? dst0 : dst1;
    int sN = lo ? src0 : src1;
    float4 xd = ((const float4*)(x + (size_t)dN * FF))[sub & 3];
    float4 xs = ((const float4*)(x + (size_t)sN * FF))[sub & 3];

    // ---- weights for this lane's j = 8*sub .. 8*sub+7 (1 LDS.128 each) ----
    uint4 wau = *(const uint4*)(sWa + 4 * sub);
    uint4 wbu = *(const uint4*)(sWb + 4 * sub);
    const __half2* wa = (const __half2*)&wau;
    const __half2* wb = (const __half2*)&wbu;

    // ---- packed half2 dots ----
    const __half2* ph0 = (const __half2*)&pu0;
    const __half2* qh0 = (const __half2*)&qu0;
    const __half2* ph1 = (const __half2*)&pu1;
    const __half2* qh1 = (const __half2*)&qu1;
    const __half2 z2 = __float2half2_rn(0.0f);
    __half2 avh0 = z2, bvh0 = z2, avh1 = z2, bvh1 = z2;
#pragma unroll
    for (int t = 0; t < 4; t++) {
        __half2 hh0 = __hmax2(__hadd2(ph0[t], qh0[t]), z2);
        __half2 hh1 = __hmax2(__hadd2(ph1[t], qh1[t]), z2);
        avh0 = __hfma2(hh0, wa[t], avh0);
        bvh0 = __hfma2(hh0, wb[t], bvh0);
        avh1 = __hfma2(hh1, wa[t], avh1);
        bvh1 = __hfma2(hh1, wb[t], bvh1);
    }
    float2 fa0 = __half22float2(avh0);
    float2 fb0 = __half22float2(bvh0);
    float2 fa1 = __half22float2(avh1);
    float2 fb1 = __half22float2(bvh1);
    float av0 = fa0.x + fa0.y, bv0 = fb0.x + fb0.y;
    float av1 = fa1.x + fa1.y, bv1 = fb1.x + fb1.y;

    // ---- reduce: 2 butterfly rounds, then select-swap across halves ----
#pragma unroll
    for (int m = 1; m < 4; m <<= 1) {
        av0 += __shfl_xor_sync(0xffffffffu, av0, m);
        bv0 += __shfl_xor_sync(0xffffffffu, bv0, m);
        av1 += __shfl_xor_sync(0xffffffffu, av1, m);
        bv1 += __shfl_xor_sync(0xffffffffu, bv1, m);
    }
    float va = lo ? av1 : av0;
    float vb = lo ? bv1 : bv0;
    float ra = __shfl_xor_sync(0xffffffffu, va, 4);
    float rb = __shfl_xor_sync(0xffffffffu, vb, 4);
    float a  = (lo ? av0 : av1) + ra + b2[0];
    float b  = (lo ? bv0 : bv1) + rb + b2[1];

    // ---- epilogue: lane owns 4 floats of its edge's 16-float output ----
    long long e = lo ? e0 : (e0 + 1);
    float4 o;
    o.x = a * (xd.x - b * xs.x);
    o.y = a * (xd.y - b * xs.y);
    o.z = a * (xd.z - b * xs.z);
    o.w = a * (xd.w - b * xs.w);
    ((float4*)(out + (size_t)e * FF))[sub & 3] = o;
}

// ---------------------------------------------------------------------------
// Launch
// ---------------------------------------------------------------------------
extern "C" void kernel_launch(void* const* d_in, const int* in_sizes, int n_in,
                              void* d_out, int out_size)
{
    const float* x   = (const float*)d_in[0];   // [N,16]
    const int*   ei  = (const int*)d_in[1];     // [2,E] int32
    const float* W1  = (const float*)d_in[2];   // [32,64]
    const float* b1  = (const float*)d_in[3];   // [64]
    const float* W2  = (const float*)d_in[4];   // [64,2]
    const float* b2  = (const float*)d_in[5];   // [2]
    float*       out = (float*)d_out;           // [E,16]

    (void)in_sizes; (void)n_in; (void)out_size;

    precompute_kernel<<<1184, 256>>>(x, W1, b1);

    {
        long long total = (long long)(EE / 2) * 8;   // 12.8M threads
        int threads = 256;
        int blocks = (int)((total + threads - 1) / threads);
        edge_kernel<<<blocks, threads>>>(x, ei, W2, b2, out);
    }
}